// round 3
// baseline (speedup 1.0000x reference)
#include <cuda_runtime.h>

#define MARGIN 0.5f
#define WARPS_PER_BLOCK 16

// Scratch accumulators (no device allocation allowed -> __device__ globals).
// Zero at module load; the last block re-zeros them each call, so every
// kernel_launch sees the same initial state (deterministic, graph-safe).
__device__ float        g_total;
__device__ unsigned int g_count;
__device__ unsigned int g_arrive;

// One warp per problem. Lanes cooperatively hold the neg scores (2 regs cover
// N<=64); 16 lanes hold pos scores; inner loop is uniform length pc -> no
// ragged-count divergence. All loads issued up-front and unconditionally
// (indices are always in [0,C) regardless of counts) so counts/indices/gathers
// overlap instead of forming a 3-deep serial chain; count masks applied as
// SELs afterward. Fence-free finalize: release REDs + acq_rel ticket (no
// __threadfence -> no CCTL.IVALL L1 flush, which killed round 2).
__global__ void __launch_bounds__(WARPS_PER_BLOCK * 32)
mpcl_fused_kernel(const float* __restrict__ scores,
                  const int*   __restrict__ pos_indices,
                  const int*   __restrict__ neg_indices,
                  const int*   __restrict__ pos_counts,
                  const int*   __restrict__ neg_counts,
                  float*       __restrict__ out,
                  int B, int C, int P, int N)
{
    __shared__ float    s_tot[WARPS_PER_BLOCK];
    __shared__ unsigned s_cnt[WARPS_PER_BLOCK];

    const int warp = threadIdx.x >> 5;
    const int lane = threadIdx.x & 31;
    const int b    = blockIdx.x * WARPS_PER_BLOCK + warp;

    float    acc = 0.0f;
    unsigned cnt = 0u;

    if (b < B) {
        const float* s  = scores      + (size_t)b * (size_t)C;
        const int*   ni = neg_indices + (size_t)b * (size_t)N;
        const int*   pi = pos_indices + (size_t)b * (size_t)P;

        // Issue everything independent up front (MLP). Index arrays are fully
        // populated with values in [0, C), so unconditional loads are safe.
        const int pc = pos_counts[b];             // broadcast (1 addr / warp)
        const int nc = neg_counts[b];
        const int i0 = ni[lane];
        const int i1 = (lane + 32 < N) ? ni[lane + 32] : i0;
        const int ip = pi[lane & (32 - 1) & 15];  // lanes 0..15 matter (P<=16)

        float n0 = s[i0];
        float n1 = s[i1];
        float pv = s[ip];

        // Mask invalid slots: -1e30 makes relu(a + neg) exactly 0.
        n0 = (lane < nc)      ? n0 : -1e30f;
        n1 = (lane + 32 < nc) ? n1 : -1e30f;

        cnt = (unsigned)(pc * ((nc > 0) ? nc : 0));
        if (nc == 0) pv = pv;  // no-op; loop below guarded by pc only, negs masked

        const int iters = (nc > 0) ? pc : 0;
        for (int p = 0; p < iters; p++) {
            const float a = MARGIN - __shfl_sync(0xffffffffu, pv, p);
            acc += fmaxf(a + n0, 0.0f);
            acc += fmaxf(a + n1, 0.0f);
        }
    }

    // Warp reduction of acc (cnt complete on lane 0 already)
    #pragma unroll
    for (int o = 16; o > 0; o >>= 1)
        acc += __shfl_xor_sync(0xffffffffu, acc, o);

    if (lane == 0) {
        s_tot[warp] = acc;
        s_cnt[warp] = cnt;
    }
    __syncthreads();

    if (threadIdx.x == 0) {
        float    t = 0.0f;
        unsigned c = 0u;
        #pragma unroll
        for (int w = 0; w < WARPS_PER_BLOCK; w++) {
            t += s_tot[w];
            c += s_cnt[w];
        }
        // Release REDs: order our partials before the ticket without any
        // L1-flushing fence.
        asm volatile("red.add.release.gpu.f32 [%0], %1;"
                     :: "l"(&g_total), "f"(t) : "memory");
        asm volatile("red.add.release.gpu.u32 [%0], %1;"
                     :: "l"(&g_count), "r"(c) : "memory");
        unsigned ticket;
        asm volatile("atom.add.acq_rel.gpu.u32 %0, [%1], %2;"
                     : "=r"(ticket) : "l"(&g_arrive), "r"(1u) : "memory");

        if (ticket == (unsigned)gridDim.x - 1u) {
            // Acquire loads: guaranteed to see every block's released REDs.
            float    tv;
            unsigned cv;
            asm volatile("ld.acquire.gpu.f32 %0, [%1];"
                         : "=f"(tv) : "l"(&g_total) : "memory");
            asm volatile("ld.acquire.gpu.u32 %0, [%1];"
                         : "=r"(cv) : "l"(&g_count) : "memory");
            out[0] = (cv > 0u) ? (tv / (float)cv) : 0.0f;
            // Reset for the next (graph-replayed) call; kernel-end implicit
            // fence makes these visible to the next launch.
            g_total  = 0.0f;
            g_count  = 0u;
            g_arrive = 0u;
        }
    }
}

extern "C" void kernel_launch(void* const* d_in, const int* in_sizes, int n_in,
                              void* d_out, int out_size)
{
    const float* scores      = (const float*)d_in[0];
    const int*   pos_indices = (const int*)  d_in[1];
    const int*   neg_indices = (const int*)  d_in[2];
    const int*   pos_counts  = (const int*)  d_in[3];
    const int*   neg_counts  = (const int*)  d_in[4];
    float*       out         = (float*)d_out;

    const int B = in_sizes[3];             // pos_counts element count
    const int C = in_sizes[0] / B;         // candidates per problem
    const int P = in_sizes[1] / B;         // max positives
    const int N = in_sizes[2] / B;         // max negatives

    const int blocks = (B + WARPS_PER_BLOCK - 1) / WARPS_PER_BLOCK;
    mpcl_fused_kernel<<<blocks, WARPS_PER_BLOCK * 32>>>(
        scores, pos_indices, neg_indices, pos_counts, neg_counts, out,
        B, C, P, N);
}